// round 2
// baseline (speedup 1.0000x reference)
#include <cuda_runtime.h>
#include <math.h>

#define SEQ 4096
#define DIM 1024
#define NH  16
#define HD  64

// Scratch (allocation-free rule: __device__ globals)
__device__ float g_Q[SEQ * DIM];
__device__ float g_K[SEQ * DIM];
__device__ float g_V[SEQ * DIM];
__device__ float g_ctx[SEQ * DIM];

// ---------------------------------------------------------------------------
// SGEMM core: C[M,N] = A[M,K] @ B[N,K]^T (+ bias), M mult of 128, N=K=1024.
// 128x128x8 tile, 256 threads, 8x8 per-thread with split-tile (4+4) blocking.
// ---------------------------------------------------------------------------
__device__ __forceinline__ void gemm128(const float* __restrict__ A,
                                        const float* __restrict__ B,
                                        float* __restrict__ C,
                                        const float* __restrict__ bias)
{
    constexpr int K = 1024;
    constexpr int N = 1024;
    __shared__ float As[8][132];
    __shared__ float Bs[8][132];

    const int tid = threadIdx.x;
    const int m0 = blockIdx.y * 128;
    const int n0 = blockIdx.x * 128;

    const int lrow = tid >> 1;          // 0..127
    const int lk4  = (tid & 1) << 2;    // 0 or 4
    const float* Aptr = A + (size_t)(m0 + lrow) * K + lk4;
    const float* Bptr = B + (size_t)(n0 + lrow) * K + lk4;

    const int ty = tid >> 4;            // 0..15
    const int tx = tid & 15;            // 0..15

    float acc[8][8];
#pragma unroll
    for (int i = 0; i < 8; i++)
#pragma unroll
        for (int j = 0; j < 8; j++) acc[i][j] = 0.0f;

    for (int k0 = 0; k0 < K; k0 += 8) {
        float4 av = *(const float4*)(Aptr + k0);
        float4 bv = *(const float4*)(Bptr + k0);
        As[lk4 + 0][lrow] = av.x; As[lk4 + 1][lrow] = av.y;
        As[lk4 + 2][lrow] = av.z; As[lk4 + 3][lrow] = av.w;
        Bs[lk4 + 0][lrow] = bv.x; Bs[lk4 + 1][lrow] = bv.y;
        Bs[lk4 + 2][lrow] = bv.z; Bs[lk4 + 3][lrow] = bv.w;
        __syncthreads();

#pragma unroll
        for (int k = 0; k < 8; k++) {
            float a[8], b[8];
            *(float4*)&a[0] = *(const float4*)&As[k][ty * 4];
            *(float4*)&a[4] = *(const float4*)&As[k][64 + ty * 4];
            *(float4*)&b[0] = *(const float4*)&Bs[k][tx * 4];
            *(float4*)&b[4] = *(const float4*)&Bs[k][64 + tx * 4];
#pragma unroll
            for (int i = 0; i < 8; i++)
#pragma unroll
                for (int j = 0; j < 8; j++) acc[i][j] = fmaf(a[i], b[j], acc[i][j]);
        }
        __syncthreads();
    }

    float4 bias0 = make_float4(0.f, 0.f, 0.f, 0.f);
    float4 bias1 = make_float4(0.f, 0.f, 0.f, 0.f);
    if (bias != nullptr) {
        bias0 = *(const float4*)&bias[n0 + tx * 4];
        bias1 = *(const float4*)&bias[n0 + 64 + tx * 4];
    }

#pragma unroll
    for (int i = 0; i < 8; i++) {
        const int row = m0 + ((i < 4) ? (ty * 4 + i) : (64 + ty * 4 + (i - 4)));
        float4 v0 = make_float4(acc[i][0] + bias0.x, acc[i][1] + bias0.y,
                                acc[i][2] + bias0.z, acc[i][3] + bias0.w);
        float4 v1 = make_float4(acc[i][4] + bias1.x, acc[i][5] + bias1.y,
                                acc[i][6] + bias1.z, acc[i][7] + bias1.w);
        *(float4*)&C[(size_t)row * N + n0 + tx * 4] = v0;
        *(float4*)&C[(size_t)row * N + n0 + 64 + tx * 4] = v1;
    }
}

__global__ __launch_bounds__(256) void qkv_gemm_kernel(const float* __restrict__ x,
                                                       const float* __restrict__ Wq,
                                                       const float* __restrict__ Wk,
                                                       const float* __restrict__ Wv)
{
    const float* B = (blockIdx.z == 0) ? Wq : ((blockIdx.z == 1) ? Wk : Wv);
    float* C       = (blockIdx.z == 0) ? g_Q : ((blockIdx.z == 1) ? g_K : g_V);
    gemm128(x, B, C, nullptr);
}

__global__ __launch_bounds__(256) void out_gemm_kernel(const float* __restrict__ Wo,
                                                       const float* __restrict__ bo,
                                                       float* __restrict__ out)
{
    gemm128(g_ctx, Wo, out, bo);
}

// ---------------------------------------------------------------------------
// Flash attention, causal. Br=Bc=64, 256 threads, 4x4 per-thread tiles.
// Q/K/P stored k-major (transposed) in smem; V natural. Stride 68 (16B aligned).
// ---------------------------------------------------------------------------
__global__ __launch_bounds__(256) void attn_kernel()
{
    extern __shared__ float sm[];
    float* Qs = sm;                 // [64][68]  Qs[d][r], pre-scaled by 1/8
    float* Ks = Qs + 64 * 68;       // [64][68]  Ks[d][c]
    float* Ps = Ks + 64 * 68;       // [64][68]  Ps[c][r]
    float* Vs = Ps + 64 * 68;       // [64][68]  Vs[c][x]

    const int qb = blockIdx.x;      // 0..63
    const int h  = blockIdx.y;      // 0..15
    const int hc = h * HD;
    const int tid = threadIdx.x;
    const int ty = tid >> 4;        // 0..15  -> rows ty*4..ty*4+3
    const int tx = tid & 15;        // 0..15  -> cols tx*4..tx*4+3

    // Load Q tile transposed, folding in 1/sqrt(HD) = 0.125
#pragma unroll
    for (int it = 0; it < 4; it++) {
        int id = tid + it * 256;            // 0..1023 float4 slots
        int r = id >> 4;
        int dseg = (id & 15) << 2;
        float4 v = *(const float4*)&g_Q[(size_t)(qb * 64 + r) * DIM + hc + dseg];
        Qs[(dseg + 0) * 68 + r] = v.x * 0.125f;
        Qs[(dseg + 1) * 68 + r] = v.y * 0.125f;
        Qs[(dseg + 2) * 68 + r] = v.z * 0.125f;
        Qs[(dseg + 3) * 68 + r] = v.w * 0.125f;
    }

    float m[4], l[4], o[4][4];
#pragma unroll
    for (int i = 0; i < 4; i++) {
        m[i] = -1e30f; l[i] = 0.0f;
#pragma unroll
        for (int j = 0; j < 4; j++) o[i][j] = 0.0f;
    }

    for (int kv = 0; kv <= qb; kv++) {
        __syncthreads();   // prev PV reads of Ks/Vs/Ps done
#pragma unroll
        for (int it = 0; it < 4; it++) {
            int id = tid + it * 256;
            int r = id >> 4;
            int dseg = (id & 15) << 2;
            float4 kvv = *(const float4*)&g_K[(size_t)(kv * 64 + r) * DIM + hc + dseg];
            Ks[(dseg + 0) * 68 + r] = kvv.x;
            Ks[(dseg + 1) * 68 + r] = kvv.y;
            Ks[(dseg + 2) * 68 + r] = kvv.z;
            Ks[(dseg + 3) * 68 + r] = kvv.w;
            float4 vv = *(const float4*)&g_V[(size_t)(kv * 64 + r) * DIM + hc + dseg];
            *(float4*)&Vs[r * 68 + dseg] = vv;
        }
        __syncthreads();   // K/V tiles ready

        // S = (Q/8) @ K^T  (4x4 per thread)
        float s[4][4];
#pragma unroll
        for (int i = 0; i < 4; i++)
#pragma unroll
            for (int j = 0; j < 4; j++) s[i][j] = 0.0f;

#pragma unroll 4
        for (int d = 0; d < 64; d++) {
            float4 qa = *(const float4*)&Qs[d * 68 + ty * 4];
            float4 kb = *(const float4*)&Ks[d * 68 + tx * 4];
            float qr[4] = {qa.x, qa.y, qa.z, qa.w};
            float kc[4] = {kb.x, kb.y, kb.z, kb.w};
#pragma unroll
            for (int i = 0; i < 4; i++)
#pragma unroll
                for (int j = 0; j < 4; j++) s[i][j] = fmaf(qr[i], kc[j], s[i][j]);
        }

        // causal mask on diagonal block
        if (kv == qb) {
#pragma unroll
            for (int i = 0; i < 4; i++)
#pragma unroll
                for (int j = 0; j < 4; j++)
                    if (tx * 4 + j > ty * 4 + i) s[i][j] = -1e30f;
        }

        // online softmax
#pragma unroll
        for (int i = 0; i < 4; i++) {
            float mx = fmaxf(fmaxf(s[i][0], s[i][1]), fmaxf(s[i][2], s[i][3]));
#pragma unroll
            for (int off = 1; off < 16; off <<= 1)
                mx = fmaxf(mx, __shfl_xor_sync(0xffffffffu, mx, off));
            float mn = fmaxf(m[i], mx);
            float fac = __expf(m[i] - mn);
            m[i] = mn;
            float sum = 0.0f;
#pragma unroll
            for (int j = 0; j < 4; j++) {
                s[i][j] = __expf(s[i][j] - mn);
                sum += s[i][j];
            }
#pragma unroll
            for (int off = 1; off < 16; off <<= 1)
                sum += __shfl_xor_sync(0xffffffffu, sum, off);
            l[i] = l[i] * fac + sum;
#pragma unroll
            for (int j = 0; j < 4; j++) o[i][j] *= fac;
        }

        // write P transposed: Ps[c][r]
#pragma unroll
        for (int i = 0; i < 4; i++)
#pragma unroll
            for (int j = 0; j < 4; j++)
                Ps[(tx * 4 + j) * 68 + ty * 4 + i] = s[i][j];
        __syncthreads();   // P visible

        // O += P @ V
#pragma unroll 4
        for (int c = 0; c < 64; c++) {
            float4 pa = *(const float4*)&Ps[c * 68 + ty * 4];
            float4 vb = *(const float4*)&Vs[c * 68 + tx * 4];
            float pr[4] = {pa.x, pa.y, pa.z, pa.w};
            float vc[4] = {vb.x, vb.y, vb.z, vb.w};
#pragma unroll
            for (int i = 0; i < 4; i++)
#pragma unroll
                for (int j = 0; j < 4; j++) o[i][j] = fmaf(pr[i], vc[j], o[i][j]);
        }
    }

    // epilogue: normalize and store ctx in [s, h*HD + x] layout
#pragma unroll
    for (int i = 0; i < 4; i++) {
        float inv = 1.0f / l[i];
        int row = qb * 64 + ty * 4 + i;
        float4 v = make_float4(o[i][0] * inv, o[i][1] * inv,
                               o[i][2] * inv, o[i][3] * inv);
        *(float4*)&g_ctx[(size_t)row * DIM + hc + tx * 4] = v;
    }
}

extern "C" void kernel_launch(void* const* d_in, const int* in_sizes, int n_in,
                              void* d_out, int out_size)
{
    (void)in_sizes; (void)n_in; (void)out_size;
    const float* x  = (const float*)d_in[0];
    const float* Wq = (const float*)d_in[1];
    const float* Wk = (const float*)d_in[2];
    const float* Wv = (const float*)d_in[3];
    const float* Wo = (const float*)d_in[4];
    const float* bo = (const float*)d_in[5];
    float* out = (float*)d_out;

    static bool attr_set = false;
    if (!attr_set) {
        cudaFuncSetAttribute(attn_kernel,
                             cudaFuncAttributeMaxDynamicSharedMemorySize,
                             4 * 64 * 68 * (int)sizeof(float));
        attr_set = true;
    }

    // 1) Q, K, V projections (fused into one launch over z)
    {
        dim3 grid(1024 / 128, SEQ / 128, 3);
        qkv_gemm_kernel<<<grid, 256>>>(x, Wq, Wk, Wv);
    }
    // 2) causal flash attention
    {
        dim3 grid(SEQ / 64, NH);
        attn_kernel<<<grid, 256, 4 * 64 * 68 * (int)sizeof(float)>>>();
    }
    // 3) output projection + bias
    {
        dim3 grid(1024 / 128, SEQ / 128, 1);
        out_gemm_kernel<<<grid, 256>>>(Wo, bo, out);
    }
}

// round 5
// speedup vs baseline: 1.1937x; 1.1937x over previous
#include <cuda_runtime.h>
#include <math.h>

#define SEQ 4096
#define DIM 1024
#define NH  16
#define HD  64

// Scratch (allocation-free rule: __device__ globals)
__device__ float g_Q[SEQ * DIM];
__device__ float g_K[SEQ * DIM];
__device__ float g_V[SEQ * DIM];
__device__ float g_ctx[SEQ * DIM];

// ---------------------------------------------------------------------------
// SGEMM core: C[M,N] = A[M,K] @ B[N,K]^T (+ bias), N=K=1024.
// 128x128x8 tile, 256 threads, 8x8 per thread, DOUBLE-BUFFERED smem
// (one __syncthreads per k-tile, LDG of next tile overlapped with FMA).
// ---------------------------------------------------------------------------
__device__ __forceinline__ void gemm128(const float* __restrict__ A,
                                        const float* __restrict__ B,
                                        float* __restrict__ C,
                                        const float* __restrict__ bias)
{
    constexpr int K = 1024;
    constexpr int N = 1024;
    __shared__ float As[2][8][132];
    __shared__ float Bs[2][8][132];

    const int tid = threadIdx.x;
    const int m0 = blockIdx.y * 128;
    const int n0 = blockIdx.x * 128;

    const int lrow = tid >> 1;          // 0..127
    const int lk4  = (tid & 1) << 2;    // 0 or 4
    const float* Aptr = A + (size_t)(m0 + lrow) * K + lk4;
    const float* Bptr = B + (size_t)(n0 + lrow) * K + lk4;

    const int ty = tid >> 4;            // 0..15
    const int tx = tid & 15;            // 0..15

    float acc[8][8];
#pragma unroll
    for (int i = 0; i < 8; i++)
#pragma unroll
        for (int j = 0; j < 8; j++) acc[i][j] = 0.0f;

    // prologue: load k-tile 0 into buffer 0
    {
        float4 av = *(const float4*)(Aptr);
        float4 bv = *(const float4*)(Bptr);
        As[0][lk4 + 0][lrow] = av.x; As[0][lk4 + 1][lrow] = av.y;
        As[0][lk4 + 2][lrow] = av.z; As[0][lk4 + 3][lrow] = av.w;
        Bs[0][lk4 + 0][lrow] = bv.x; Bs[0][lk4 + 1][lrow] = bv.y;
        Bs[0][lk4 + 2][lrow] = bv.z; Bs[0][lk4 + 3][lrow] = bv.w;
    }
    __syncthreads();

    int buf = 0;
    for (int k0 = 8; k0 < K; k0 += 8) {
        // fetch next tile (overlaps with FMA below)
        float4 an = *(const float4*)(Aptr + k0);
        float4 bn = *(const float4*)(Bptr + k0);

#pragma unroll
        for (int k = 0; k < 8; k++) {
            float a[8], b[8];
            *(float4*)&a[0] = *(const float4*)&As[buf][k][ty * 4];
            *(float4*)&a[4] = *(const float4*)&As[buf][k][64 + ty * 4];
            *(float4*)&b[0] = *(const float4*)&Bs[buf][k][tx * 4];
            *(float4*)&b[4] = *(const float4*)&Bs[buf][k][64 + tx * 4];
#pragma unroll
            for (int i = 0; i < 8; i++)
#pragma unroll
                for (int j = 0; j < 8; j++) acc[i][j] = fmaf(a[i], b[j], acc[i][j]);
        }

        const int nb = buf ^ 1;
        As[nb][lk4 + 0][lrow] = an.x; As[nb][lk4 + 1][lrow] = an.y;
        As[nb][lk4 + 2][lrow] = an.z; As[nb][lk4 + 3][lrow] = an.w;
        Bs[nb][lk4 + 0][lrow] = bn.x; Bs[nb][lk4 + 1][lrow] = bn.y;
        Bs[nb][lk4 + 2][lrow] = bn.z; Bs[nb][lk4 + 3][lrow] = bn.w;
        __syncthreads();
        buf = nb;
    }

    // last k-tile
#pragma unroll
    for (int k = 0; k < 8; k++) {
        float a[8], b[8];
        *(float4*)&a[0] = *(const float4*)&As[buf][k][ty * 4];
        *(float4*)&a[4] = *(const float4*)&As[buf][k][64 + ty * 4];
        *(float4*)&b[0] = *(const float4*)&Bs[buf][k][tx * 4];
        *(float4*)&b[4] = *(const float4*)&Bs[buf][k][64 + tx * 4];
#pragma unroll
        for (int i = 0; i < 8; i++)
#pragma unroll
            for (int j = 0; j < 8; j++) acc[i][j] = fmaf(a[i], b[j], acc[i][j]);
    }

    float4 bias0 = make_float4(0.f, 0.f, 0.f, 0.f);
    float4 bias1 = make_float4(0.f, 0.f, 0.f, 0.f);
    if (bias != nullptr) {
        bias0 = *(const float4*)&bias[n0 + tx * 4];
        bias1 = *(const float4*)&bias[n0 + 64 + tx * 4];
    }

#pragma unroll
    for (int i = 0; i < 8; i++) {
        const int row = m0 + ((i < 4) ? (ty * 4 + i) : (64 + ty * 4 + (i - 4)));
        float4 v0 = make_float4(acc[i][0] + bias0.x, acc[i][1] + bias0.y,
                                acc[i][2] + bias0.z, acc[i][3] + bias0.w);
        float4 v1 = make_float4(acc[i][4] + bias1.x, acc[i][5] + bias1.y,
                                acc[i][6] + bias1.z, acc[i][7] + bias1.w);
        *(float4*)&C[(size_t)row * N + n0 + tx * 4] = v0;
        *(float4*)&C[(size_t)row * N + n0 + 64 + tx * 4] = v1;
    }
}

__global__ __launch_bounds__(256) void qkv_gemm_kernel(const float* __restrict__ x,
                                                       const float* __restrict__ Wq,
                                                       const float* __restrict__ Wk,
                                                       const float* __restrict__ Wv)
{
    const float* B = (blockIdx.z == 0) ? Wq : ((blockIdx.z == 1) ? Wk : Wv);
    float* C       = (blockIdx.z == 0) ? g_Q : ((blockIdx.z == 1) ? g_K : g_V);
    gemm128(x, B, C, nullptr);
}

__global__ __launch_bounds__(256) void out_gemm_kernel(const float* __restrict__ Wo,
                                                       const float* __restrict__ bo,
                                                       float* __restrict__ out)
{
    gemm128(g_ctx, Wo, out, bo);
}

// ---------------------------------------------------------------------------
// Flash attention, causal. Br=Bc=128, 256 threads, 8x8 per-thread S tiles.
// Q/K/P k-major (transposed) in smem; V natural. 170KB smem, 1 CTA/SM.
// Row split: R(i) = ty*4+i (i<4) / 64+ty*4+(i-4); cols C(j) analogous on tx.
// ---------------------------------------------------------------------------
__global__ __launch_bounds__(256) void attn_kernel()
{
    extern __shared__ float sm[];
    float* Qs = sm;                  // [64][132]   Qs[d][r], pre-scaled 1/8
    float* Ks = Qs + 64 * 132;       // [64][132]   Ks[d][c]
    float* Ps = Ks + 64 * 132;       // [128][132]  Ps[c][r]
    float* Vs = Ps + 128 * 132;      // [128][68]   Vs[c][x]

    // reverse order: biggest q-blocks launch first (load balance)
    const int qb = (gridDim.x - 1) - blockIdx.x;    // 0..31
    const int h  = blockIdx.y;                      // 0..15
    const int hc = h * HD;
    const int tid = threadIdx.x;
    const int ty = tid >> 4;         // 0..15
    const int tx = tid & 15;         // 0..15
    const int r0 = ty * 4;
    const int c0 = tx * 4;

    // Load Q tile (128 rows) transposed, folding in 1/sqrt(64) = 0.125
#pragma unroll
    for (int it = 0; it < 8; it++) {
        int id = tid + it * 256;             // 0..2047 float4 slots
        int r = id >> 4;                     // 0..127
        int dseg = (id & 15) << 2;           // 0..60
        float4 v = *(const float4*)&g_Q[(size_t)(qb * 128 + r) * DIM + hc + dseg];
        Qs[(dseg + 0) * 132 + r] = v.x * 0.125f;
        Qs[(dseg + 1) * 132 + r] = v.y * 0.125f;
        Qs[(dseg + 2) * 132 + r] = v.z * 0.125f;
        Qs[(dseg + 3) * 132 + r] = v.w * 0.125f;
    }

    float m[8], l[8], o[8][4];
#pragma unroll
    for (int i = 0; i < 8; i++) {
        m[i] = -1e30f; l[i] = 0.0f;
#pragma unroll
        for (int j = 0; j < 4; j++) o[i][j] = 0.0f;
    }

    for (int kb = 0; kb <= qb; kb++) {
        __syncthreads();   // prev PV reads of Ps/Vs done; Ks S-reads done; (iter0: Qs ready)
#pragma unroll
        for (int it = 0; it < 8; it++) {
            int id = tid + it * 256;
            int c = id >> 4;                 // 0..127
            int dseg = (id & 15) << 2;
            float4 kv4 = *(const float4*)&g_K[(size_t)(kb * 128 + c) * DIM + hc + dseg];
            Ks[(dseg + 0) * 132 + c] = kv4.x;
            Ks[(dseg + 1) * 132 + c] = kv4.y;
            Ks[(dseg + 2) * 132 + c] = kv4.z;
            Ks[(dseg + 3) * 132 + c] = kv4.w;
            float4 vv = *(const float4*)&g_V[(size_t)(kb * 128 + c) * DIM + hc + dseg];
            *(float4*)&Vs[c * 68 + dseg] = vv;
        }
        __syncthreads();   // K/V tiles ready

        // S = (Q/8) @ K^T   (8x8 per thread)
        float s[8][8];
#pragma unroll
        for (int i = 0; i < 8; i++)
#pragma unroll
            for (int j = 0; j < 8; j++) s[i][j] = 0.0f;

#pragma unroll 4
        for (int d = 0; d < 64; d++) {
            float a[8], b[8];
            *(float4*)&a[0] = *(const float4*)&Qs[d * 132 + r0];
            *(float4*)&a[4] = *(const float4*)&Qs[d * 132 + 64 + r0];
            *(float4*)&b[0] = *(const float4*)&Ks[d * 132 + c0];
            *(float4*)&b[4] = *(const float4*)&Ks[d * 132 + 64 + c0];
#pragma unroll
            for (int i = 0; i < 8; i++)
#pragma unroll
                for (int j = 0; j < 8; j++) s[i][j] = fmaf(a[i], b[j], s[i][j]);
        }

        // causal mask on diagonal block (block-local row/col compare)
        if (kb == qb) {
#pragma unroll
            for (int i = 0; i < 8; i++) {
                int R = r0 + i + ((i < 4) ? 0 : 60);
#pragma unroll
                for (int j = 0; j < 8; j++) {
                    int Cc = c0 + j + ((j < 4) ? 0 : 60);
                    if (Cc > R) s[i][j] = -1e30f;
                }
            }
        }

        // online softmax (row groups = 16 lanes sharing ty)
#pragma unroll
        for (int i = 0; i < 8; i++) {
            float mx = s[i][0];
#pragma unroll
            for (int j = 1; j < 8; j++) mx = fmaxf(mx, s[i][j]);
#pragma unroll
            for (int off = 1; off < 16; off <<= 1)
                mx = fmaxf(mx, __shfl_xor_sync(0xffffffffu, mx, off));
            float mn = fmaxf(m[i], mx);
            float fac = __expf(m[i] - mn);
            m[i] = mn;
            float sum = 0.0f;
#pragma unroll
            for (int j = 0; j < 8; j++) {
                s[i][j] = __expf(s[i][j] - mn);
                sum += s[i][j];
            }
#pragma unroll
            for (int off = 1; off < 16; off <<= 1)
                sum += __shfl_xor_sync(0xffffffffu, sum, off);
            l[i] = l[i] * fac + sum;
#pragma unroll
            for (int j = 0; j < 4; j++) o[i][j] *= fac;
        }

        // write P transposed: Ps[c][r]
#pragma unroll
        for (int i = 0; i < 8; i++) {
            int R = r0 + i + ((i < 4) ? 0 : 60);
#pragma unroll
            for (int j = 0; j < 8; j++) {
                int Cc = c0 + j + ((j < 4) ? 0 : 60);
                Ps[Cc * 132 + R] = s[i][j];
            }
        }
        __syncthreads();   // P visible

        // O += P @ V   (8 rows x 4 cols per thread)
#pragma unroll 4
        for (int c = 0; c < 128; c++) {
            float p[8];
            *(float4*)&p[0] = *(const float4*)&Ps[c * 132 + r0];
            *(float4*)&p[4] = *(const float4*)&Ps[c * 132 + 64 + r0];
            float4 vb = *(const float4*)&Vs[c * 68 + c0];
            float v4[4] = {vb.x, vb.y, vb.z, vb.w};
#pragma unroll
            for (int i = 0; i < 8; i++)
#pragma unroll
                for (int j = 0; j < 4; j++) o[i][j] = fmaf(p[i], v4[j], o[i][j]);
        }
    }

    // epilogue: normalize and store ctx
#pragma unroll
    for (int i = 0; i < 8; i++) {
        float inv = 1.0f / l[i];
        int R = r0 + i + ((i < 4) ? 0 : 60);
        int row = qb * 128 + R;
        float4 v = make_float4(o[i][0] * inv, o[i][1] * inv,
                               o[i][2] * inv, o[i][3] * inv);
        *(float4*)&g_ctx[(size_t)row * DIM + hc + c0] = v;
    }
}

#define ATTN_SMEM ((64 * 132 + 64 * 132 + 128 * 132 + 128 * 68) * (int)sizeof(float))

extern "C" void kernel_launch(void* const* d_in, const int* in_sizes, int n_in,
                              void* d_out, int out_size)
{
    (void)in_sizes; (void)n_in; (void)out_size;
    const float* x  = (const float*)d_in[0];
    const float* Wq = (const float*)d_in[1];
    const float* Wk = (const float*)d_in[2];
    const float* Wv = (const float*)d_in[3];
    const float* Wo = (const float*)d_in[4];
    const float* bo = (const float*)d_in[5];
    float* out = (float*)d_out;

    static bool attr_set = false;
    if (!attr_set) {
        cudaFuncSetAttribute(attn_kernel,
                             cudaFuncAttributeMaxDynamicSharedMemorySize,
                             ATTN_SMEM);
        attr_set = true;
    }

    // 1) Q, K, V projections (fused into one launch over z)
    {
        dim3 grid(1024 / 128, SEQ / 128, 3);
        qkv_gemm_kernel<<<grid, 256>>>(x, Wq, Wk, Wv);
    }
    // 2) causal flash attention (Br=Bc=128)
    {
        dim3 grid(SEQ / 128, NH);
        attn_kernel<<<grid, 256, ATTN_SMEM>>>();
    }
    // 3) output projection + bias
    {
        dim3 grid(1024 / 128, SEQ / 128, 1);
        out_gemm_kernel<<<grid, 256>>>(Wo, bo, out);
    }
}

// round 8
// speedup vs baseline: 1.4400x; 1.2063x over previous
#include <cuda_runtime.h>
#include <cuda_bf16.h>
#include <cstdint>
#include <math.h>

#define SEQ 4096
#define DIM 1024
#define NH  16
#define HD  64

// ---------------------------------------------------------------------------
// Scratch (allocation-free rule: __device__ globals)
// ---------------------------------------------------------------------------
__device__ float g_Q[SEQ * DIM];
__device__ float g_K[SEQ * DIM];
__device__ float g_V[SEQ * DIM];
__device__ float g_ctx[SEQ * DIM];

// bf16 split buffers (plain row-major [rows][DIM])
__device__ __align__(16) __nv_bfloat16 g_xh[SEQ * DIM],  g_xl[SEQ * DIM];
__device__ __align__(16) __nv_bfloat16 g_ch[SEQ * DIM],  g_cl[SEQ * DIM];
__device__ __align__(16) __nv_bfloat16 g_Wqh[DIM * DIM], g_Wql[DIM * DIM];
__device__ __align__(16) __nv_bfloat16 g_Wkh[DIM * DIM], g_Wkl[DIM * DIM];
__device__ __align__(16) __nv_bfloat16 g_Wvh[DIM * DIM], g_Wvl[DIM * DIM];
__device__ __align__(16) __nv_bfloat16 g_Woh[DIM * DIM], g_Wol[DIM * DIM];

// ---------------------------------------------------------------------------
// PTX helpers: cp.async + mma.sync (baseline PTX, works at compute_103)
// ---------------------------------------------------------------------------
__device__ __forceinline__ uint32_t smem_u32(const void* p) {
    uint32_t a;
    asm("{ .reg .u64 t; cvta.to.shared.u64 t, %1; cvt.u32.u64 %0, t; }"
        : "=r"(a) : "l"(p));
    return a;
}
#define CP_ASYNC16(dst, src) \
    asm volatile("cp.async.ca.shared.global [%0], [%1], 16;" \
                 :: "r"(dst), "l"(src) : "memory")
#define CP_COMMIT()  asm volatile("cp.async.commit_group;" ::: "memory")
#define CP_WAIT1()   asm volatile("cp.async.wait_group 1;" ::: "memory")
#define CP_WAIT0()   asm volatile("cp.async.wait_group 0;" ::: "memory")

__device__ __forceinline__ void mma16816(float* c,
                                         uint32_t a0, uint32_t a1, uint32_t a2, uint32_t a3,
                                         uint32_t b0, uint32_t b1) {
    asm volatile(
        "mma.sync.aligned.m16n8k16.row.col.f32.bf16.bf16.f32 "
        "{%0,%1,%2,%3}, {%4,%5,%6,%7}, {%8,%9}, {%0,%1,%2,%3};"
        : "+f"(c[0]), "+f"(c[1]), "+f"(c[2]), "+f"(c[3])
        : "r"(a0), "r"(a1), "r"(a2), "r"(a3), "r"(b0), "r"(b1));
}

// ---------------------------------------------------------------------------
// Convert fp32 -> (bf16 hi, bf16 lo), plain row-major. 8 cols per thread.
// ---------------------------------------------------------------------------
__global__ __launch_bounds__(256) void convert_kernel(const float* __restrict__ src,
                                                      int sel, int rows)
{
    __nv_bfloat16 *dh, *dl;
    switch (sel) {
        case 0: dh = g_xh;  dl = g_xl;  break;
        case 1: dh = g_Wqh; dl = g_Wql; break;
        case 2: dh = g_Wkh; dl = g_Wkl; break;
        case 3: dh = g_Wvh; dl = g_Wvl; break;
        case 4: dh = g_Woh; dl = g_Wol; break;
        default: dh = g_ch; dl = g_cl; src = g_ctx; break;
    }
    int id = blockIdx.x * 256 + threadIdx.x;
    int r = id >> 7;
    if (r >= rows) return;
    int c = (id & 127) << 3;

    float4 v0 = *(const float4*)&src[(size_t)r * DIM + c];
    float4 v1 = *(const float4*)&src[(size_t)r * DIM + c + 4];
    float v[8] = {v0.x, v0.y, v0.z, v0.w, v1.x, v1.y, v1.z, v1.w};

    union { uint4 u; __nv_bfloat16 b[8]; } H, L;
#pragma unroll
    for (int i = 0; i < 8; i++) {
        __nv_bfloat16 h = __float2bfloat16(v[i]);
        H.b[i] = h;
        L.b[i] = __float2bfloat16(v[i] - __bfloat162float(h));
    }
    size_t off = (size_t)r * DIM + c;
    *(uint4*)&dh[off] = H.u;
    *(uint4*)&dl[off] = L.u;
}

// ---------------------------------------------------------------------------
// mma.sync bf16-split GEMM: C[M,N] = A @ B^T (+bias), A[M,1024], B[N,1024].
// CTA 128x128, 8 warps (2x4), warp tile 64x32, k-chunk 32, cp.async double buf.
// smem row stride 40 bf16 (80B) -> conflict-free quad-pattern frag loads.
// ---------------------------------------------------------------------------
#define MM_STRIDE   40                        // bf16 units per smem row
#define MAT_BYTES   (128 * MM_STRIDE * 2)     // 10240
#define STAGE_BYTES (4 * MAT_BYTES)           // 40960 (Ah, Al, Bh, Bl)
#define MM_SMEM     (2 * STAGE_BYTES)         // 81920

__device__ __forceinline__ void mm_load_chunk(uint32_t sb, int stage, int ch,
                                              const __nv_bfloat16* Ah,
                                              const __nv_bfloat16* Al,
                                              const __nv_bfloat16* Bh,
                                              const __nv_bfloat16* Bl,
                                              int mb, int nb, int tid)
{
    const uint32_t st = sb + stage * STAGE_BYTES;
#pragma unroll
    for (int it = 0; it < 2; it++) {
        int i = tid + it * 256;               // 0..511
        int r = i >> 2;                       // 0..127
        int sec = i & 3;                      // 16B section within 64B row chunk
        uint32_t d = st + r * 80 + sec * 16;
        size_t ga = (size_t)(mb * 128 + r) * DIM + ch * 32 + sec * 8;
        size_t gb = (size_t)(nb * 128 + r) * DIM + ch * 32 + sec * 8;
        CP_ASYNC16(d,                 Ah + ga);
        CP_ASYNC16(d + MAT_BYTES,     Al + ga);
        CP_ASYNC16(d + 2 * MAT_BYTES, Bh + gb);
        CP_ASYNC16(d + 3 * MAT_BYTES, Bl + gb);
    }
}

__device__ __forceinline__ void mm_tile(const __nv_bfloat16* __restrict__ Ah,
                                        const __nv_bfloat16* __restrict__ Al,
                                        const __nv_bfloat16* __restrict__ Bh,
                                        const __nv_bfloat16* __restrict__ Bl,
                                        float* __restrict__ C,
                                        const float* __restrict__ bias)
{
    extern __shared__ char smem[];
    const uint32_t sb = smem_u32(smem);
    const int tid  = threadIdx.x;
    const int wid  = tid >> 5;
    const int lane = tid & 31;
    const int wm   = wid & 1;                 // 0..1  (64-row half)
    const int wn   = wid >> 1;                // 0..3  (32-col quarter)
    const int mb   = blockIdx.y;
    const int nb   = blockIdx.x;

    const int r4 = lane >> 2;                 // 0..7
    const int kq = (lane & 3) * 2;            // 0,2,4,6

    float acc[4][4][4];
#pragma unroll
    for (int fm = 0; fm < 4; fm++)
#pragma unroll
        for (int fn = 0; fn < 4; fn++)
#pragma unroll
            for (int q = 0; q < 4; q++) acc[fm][fn][q] = 0.0f;

    mm_load_chunk(sb, 0, 0, Ah, Al, Bh, Bl, mb, nb, tid);
    CP_COMMIT();

#pragma unroll 1
    for (int ch = 0; ch < 32; ch++) {
        if (ch + 1 < 32) {
            mm_load_chunk(sb, (ch + 1) & 1, ch + 1, Ah, Al, Bh, Bl, mb, nb, tid);
            CP_COMMIT();
            CP_WAIT1();
        } else {
            CP_WAIT0();
        }
        __syncthreads();

        const uint32_t stg   = sb + (ch & 1) * STAGE_BYTES;
        const uint32_t aBase = stg + (wm * 64) * 80;
        const uint32_t bBase = stg + 2 * MAT_BYTES + (wn * 32) * 80;

#pragma unroll
        for (int ks = 0; ks < 2; ks++) {
            const uint32_t kb = (ks * 16 + kq) * 2;   // byte offset along k

            // B frags (hi & lo) for 4 n-frags
            uint32_t bh[4][2], bl[4][2];
#pragma unroll
            for (int fn = 0; fn < 4; fn++) {
                uint32_t addr = bBase + (fn * 8 + r4) * 80 + kb;
                bh[fn][0] = *(const uint32_t*)(smem + (addr - sb));
                bh[fn][1] = *(const uint32_t*)(smem + (addr - sb) + 16);
                bl[fn][0] = *(const uint32_t*)(smem + (addr - sb) + MAT_BYTES);
                bl[fn][1] = *(const uint32_t*)(smem + (addr - sb) + MAT_BYTES + 16);
            }

#pragma unroll
            for (int fm = 0; fm < 4; fm++) {
                uint32_t a0a = aBase + (fm * 16 + r4) * 80 + kb;
                uint32_t ah0 = *(const uint32_t*)(smem + (a0a - sb));
                uint32_t ah1 = *(const uint32_t*)(smem + (a0a - sb) + 8 * 80);
                uint32_t ah2 = *(const uint32_t*)(smem + (a0a - sb) + 16);
                uint32_t ah3 = *(const uint32_t*)(smem + (a0a - sb) + 8 * 80 + 16);
                uint32_t al0 = *(const uint32_t*)(smem + (a0a - sb) + MAT_BYTES);
                uint32_t al1 = *(const uint32_t*)(smem + (a0a - sb) + MAT_BYTES + 8 * 80);
                uint32_t al2 = *(const uint32_t*)(smem + (a0a - sb) + MAT_BYTES + 16);
                uint32_t al3 = *(const uint32_t*)(smem + (a0a - sb) + MAT_BYTES + 8 * 80 + 16);
#pragma unroll
                for (int fn = 0; fn < 4; fn++) {
                    mma16816(acc[fm][fn], ah0, ah1, ah2, ah3, bh[fn][0], bh[fn][1]); // hh
                    mma16816(acc[fm][fn], ah0, ah1, ah2, ah3, bl[fn][0], bl[fn][1]); // hl
                    mma16816(acc[fm][fn], al0, al1, al2, al3, bh[fn][0], bh[fn][1]); // lh
                }
            }
        }
        __syncthreads();
    }

    // epilogue
#pragma unroll
    for (int fm = 0; fm < 4; fm++) {
        const int row = mb * 128 + wm * 64 + fm * 16 + r4;
#pragma unroll
        for (int fn = 0; fn < 4; fn++) {
            const int col = nb * 128 + wn * 32 + fn * 8 + (lane & 3) * 2;
            float b0 = 0.f, b1 = 0.f;
            if (bias != nullptr) { b0 = bias[col]; b1 = bias[col + 1]; }
            float2 v0 = make_float2(acc[fm][fn][0] + b0, acc[fm][fn][1] + b1);
            float2 v1 = make_float2(acc[fm][fn][2] + b0, acc[fm][fn][3] + b1);
            *(float2*)&C[(size_t)row * DIM + col] = v0;
            *(float2*)&C[(size_t)(row + 8) * DIM + col] = v1;
        }
    }
}

__global__ __launch_bounds__(256) void mm_qkv_kernel()
{
    const __nv_bfloat16 *Bh, *Bl;
    float* C;
    if (blockIdx.z == 0)      { Bh = g_Wqh; Bl = g_Wql; C = g_Q; }
    else if (blockIdx.z == 1) { Bh = g_Wkh; Bl = g_Wkl; C = g_K; }
    else                      { Bh = g_Wvh; Bl = g_Wvl; C = g_V; }
    mm_tile(g_xh, g_xl, Bh, Bl, C, nullptr);
}

__global__ __launch_bounds__(256) void mm_out_kernel(const float* __restrict__ bo,
                                                     float* __restrict__ out)
{
    mm_tile(g_ch, g_cl, g_Woh, g_Wol, out, bo);
}

// ---------------------------------------------------------------------------
// Flash attention, causal. Br=Bc=128, 256 threads, 8x8 per-thread S tiles.
// (unchanged from round 5 passing version)
// ---------------------------------------------------------------------------
__global__ __launch_bounds__(256) void attn_kernel()
{
    extern __shared__ float sm[];
    float* Qs = sm;                  // [64][132]
    float* Ks = Qs + 64 * 132;       // [64][132]
    float* Ps = Ks + 64 * 132;       // [128][132]
    float* Vs = Ps + 128 * 132;      // [128][68]

    const int qb = (gridDim.x - 1) - blockIdx.x;
    const int h  = blockIdx.y;
    const int hc = h * HD;
    const int tid = threadIdx.x;
    const int ty = tid >> 4;
    const int tx = tid & 15;
    const int r0 = ty * 4;
    const int c0 = tx * 4;

#pragma unroll
    for (int it = 0; it < 8; it++) {
        int id = tid + it * 256;
        int r = id >> 4;
        int dseg = (id & 15) << 2;
        float4 v = *(const float4*)&g_Q[(size_t)(qb * 128 + r) * DIM + hc + dseg];
        Qs[(dseg + 0) * 132 + r] = v.x * 0.125f;
        Qs[(dseg + 1) * 132 + r] = v.y * 0.125f;
        Qs[(dseg + 2) * 132 + r] = v.z * 0.125f;
        Qs[(dseg + 3) * 132 + r] = v.w * 0.125f;
    }

    float m[8], l[8], o[8][4];
#pragma unroll
    for (int i = 0; i < 8; i++) {
        m[i] = -1e30f; l[i] = 0.0f;
#pragma unroll
        for (int j = 0; j < 4; j++) o[i][j] = 0.0f;
    }

    for (int kb = 0; kb <= qb; kb++) {
        __syncthreads();
#pragma unroll
        for (int it = 0; it < 8; it++) {
            int id = tid + it * 256;
            int c = id >> 4;
            int dseg = (id & 15) << 2;
            float4 kv4 = *(const float4*)&g_K[(size_t)(kb * 128 + c) * DIM + hc + dseg];
            Ks[(dseg + 0) * 132 + c] = kv4.x;
            Ks[(dseg + 1) * 132 + c] = kv4.y;
            Ks[(dseg + 2) * 132 + c] = kv4.z;
            Ks[(dseg + 3) * 132 + c] = kv4.w;
            float4 vv = *(const float4*)&g_V[(size_t)(kb * 128 + c) * DIM + hc + dseg];
            *(float4*)&Vs[c * 68 + dseg] = vv;
        }
        __syncthreads();

        float s[8][8];
#pragma unroll
        for (int i = 0; i < 8; i++)
#pragma unroll
            for (int j = 0; j < 8; j++) s[i][j] = 0.0f;

#pragma unroll 4
        for (int d = 0; d < 64; d++) {
            float a[8], b[8];
            *(float4*)&a[0] = *(const float4*)&Qs[d * 132 + r0];
            *(float4*)&a[4] = *(const float4*)&Qs[d * 132 + 64 + r0];
            *(float4*)&b[0] = *(const float4*)&Ks[d * 132 + c0];
            *(float4*)&b[4] = *(const float4*)&Ks[d * 132 + 64 + c0];
#pragma unroll
            for (int i = 0; i < 8; i++)
#pragma unroll
                for (int j = 0; j < 8; j++) s[i][j] = fmaf(a[i], b[j], s[i][j]);
        }

        if (kb == qb) {
#pragma unroll
            for (int i = 0; i < 8; i++) {
                int R = r0 + i + ((i < 4) ? 0 : 60);
#pragma unroll
                for (int j = 0; j < 8; j++) {
                    int Cc = c0 + j + ((j < 4) ? 0 : 60);
                    if (Cc > R) s[i][j] = -1e30f;
                }
            }
        }

#pragma unroll
        for (int i = 0; i < 8; i++) {
            float mx = s[i][0];
#pragma unroll
            for (int j = 1; j < 8; j++) mx = fmaxf(mx, s[i][j]);
#pragma unroll
            for (int off = 1; off < 16; off <<= 1)
                mx = fmaxf(mx, __shfl_xor_sync(0xffffffffu, mx, off));
            float mn = fmaxf(m[i], mx);
            float fac = __expf(m[i] - mn);
            m[i] = mn;
            float sum = 0.0f;
#pragma unroll
            for (int j = 0; j < 8; j++) {
                s[i][j] = __expf(s[i][j] - mn);
                sum += s[i][j];
            }
#pragma unroll
            for (int off = 1; off < 16; off <<= 1)
                sum += __shfl_xor_sync(0xffffffffu, sum, off);
            l[i] = l[i] * fac + sum;
#pragma unroll
            for (int j = 0; j < 4; j++) o[i][j] *= fac;
        }

#pragma unroll
        for (int i = 0; i < 8; i++) {
            int R = r0 + i + ((i < 4) ? 0 : 60);
#pragma unroll
            for (int j = 0; j < 8; j++) {
                int Cc = c0 + j + ((j < 4) ? 0 : 60);
                Ps[Cc * 132 + R] = s[i][j];
            }
        }
        __syncthreads();

#pragma unroll 4
        for (int c = 0; c < 128; c++) {
            float p[8];
            *(float4*)&p[0] = *(const float4*)&Ps[c * 132 + r0];
            *(float4*)&p[4] = *(const float4*)&Ps[c * 132 + 64 + r0];
            float4 vb = *(const float4*)&Vs[c * 68 + c0];
            float v4[4] = {vb.x, vb.y, vb.z, vb.w};
#pragma unroll
            for (int i = 0; i < 8; i++)
#pragma unroll
                for (int j = 0; j < 4; j++) o[i][j] = fmaf(p[i], v4[j], o[i][j]);
        }
    }

#pragma unroll
    for (int i = 0; i < 8; i++) {
        float inv = 1.0f / l[i];
        int R = r0 + i + ((i < 4) ? 0 : 60);
        int row = qb * 128 + R;
        float4 v = make_float4(o[i][0] * inv, o[i][1] * inv,
                               o[i][2] * inv, o[i][3] * inv);
        *(float4*)&g_ctx[(size_t)row * DIM + hc + c0] = v;
    }
}

#define ATTN_SMEM ((64 * 132 + 64 * 132 + 128 * 132 + 128 * 68) * (int)sizeof(float))

extern "C" void kernel_launch(void* const* d_in, const int* in_sizes, int n_in,
                              void* d_out, int out_size)
{
    (void)in_sizes; (void)n_in; (void)out_size;
    const float* x  = (const float*)d_in[0];
    const float* Wq = (const float*)d_in[1];
    const float* Wk = (const float*)d_in[2];
    const float* Wv = (const float*)d_in[3];
    const float* Wo = (const float*)d_in[4];
    const float* bo = (const float*)d_in[5];
    float* out = (float*)d_out;

    static bool attr_set = false;
    if (!attr_set) {
        cudaFuncSetAttribute(attn_kernel,
                             cudaFuncAttributeMaxDynamicSharedMemorySize, ATTN_SMEM);
        cudaFuncSetAttribute(mm_qkv_kernel,
                             cudaFuncAttributeMaxDynamicSharedMemorySize, MM_SMEM);
        cudaFuncSetAttribute(mm_out_kernel,
                             cudaFuncAttributeMaxDynamicSharedMemorySize, MM_SMEM);
        attr_set = true;
    }

    // 1) bf16-split conversions (x, Wq, Wk, Wv, Wo)
    convert_kernel<<<SEQ * 128 / 256, 256>>>(x,  0, SEQ);
    convert_kernel<<<DIM * 128 / 256, 256>>>(Wq, 1, DIM);
    convert_kernel<<<DIM * 128 / 256, 256>>>(Wk, 2, DIM);
    convert_kernel<<<DIM * 128 / 256, 256>>>(Wv, 3, DIM);
    convert_kernel<<<DIM * 128 / 256, 256>>>(Wo, 4, DIM);

    // 2) Q/K/V projections on tensor cores (mma.sync bf16 split)
    {
        dim3 grid(DIM / 128, SEQ / 128, 3);
        mm_qkv_kernel<<<grid, 256, MM_SMEM>>>();
    }
    // 3) causal flash attention (fp32)
    {
        dim3 grid(SEQ / 128, NH);
        attn_kernel<<<grid, 256, ATTN_SMEM>>>();
    }
    // 4) convert ctx, output projection + bias on tensor cores
    convert_kernel<<<SEQ * 128 / 256, 256>>>(nullptr, 5, SEQ);
    {
        dim3 grid(DIM / 128, SEQ / 128, 1);
        mm_out_kernel<<<grid, 256, MM_SMEM>>>(bo, out);
    }
}

// round 9
// speedup vs baseline: 2.9327x; 2.0366x over previous
#include <cuda_runtime.h>
#include <cuda_bf16.h>
#include <cstdint>
#include <math.h>

#define SEQ 4096
#define DIM 1024
#define NH  16
#define HD  64

// ---------------------------------------------------------------------------
// Scratch (allocation-free rule: __device__ globals). All bf16-split pairs.
// ---------------------------------------------------------------------------
__device__ __align__(16) __nv_bfloat16 g_xh[SEQ * DIM],  g_xl[SEQ * DIM];
__device__ __align__(16) __nv_bfloat16 g_ch[SEQ * DIM],  g_cl[SEQ * DIM];
__device__ __align__(16) __nv_bfloat16 g_Qh[SEQ * DIM],  g_Ql[SEQ * DIM];   // pre-scaled 0.125
__device__ __align__(16) __nv_bfloat16 g_Kh[SEQ * DIM],  g_Kl[SEQ * DIM];
__device__ __align__(16) __nv_bfloat16 g_Vth[DIM * SEQ], g_Vtl[DIM * SEQ];  // transposed [dim][seq]
__device__ __align__(16) __nv_bfloat16 g_Wqh[DIM * DIM], g_Wql[DIM * DIM];
__device__ __align__(16) __nv_bfloat16 g_Wkh[DIM * DIM], g_Wkl[DIM * DIM];
__device__ __align__(16) __nv_bfloat16 g_Wvh[DIM * DIM], g_Wvl[DIM * DIM];
__device__ __align__(16) __nv_bfloat16 g_Woh[DIM * DIM], g_Wol[DIM * DIM];

// ---------------------------------------------------------------------------
// PTX helpers (baseline PTX only — compute_103-safe)
// ---------------------------------------------------------------------------
__device__ __forceinline__ uint32_t smem_u32(const void* p) {
    uint32_t a;
    asm("{ .reg .u64 t; cvta.to.shared.u64 t, %1; cvt.u32.u64 %0, t; }"
        : "=r"(a) : "l"(p));
    return a;
}
#define CP_ASYNC16(dst, src) \
    asm volatile("cp.async.ca.shared.global [%0], [%1], 16;" \
                 :: "r"(dst), "l"(src) : "memory")
#define CP_COMMIT()  asm volatile("cp.async.commit_group;" ::: "memory")
#define CP_WAIT1()   asm volatile("cp.async.wait_group 1;" ::: "memory")
#define CP_WAIT0()   asm volatile("cp.async.wait_group 0;" ::: "memory")

__device__ __forceinline__ void mma16816(float* c,
                                         uint32_t a0, uint32_t a1, uint32_t a2, uint32_t a3,
                                         uint32_t b0, uint32_t b1) {
    asm volatile(
        "mma.sync.aligned.m16n8k16.row.col.f32.bf16.bf16.f32 "
        "{%0,%1,%2,%3}, {%4,%5,%6,%7}, {%8,%9}, {%0,%1,%2,%3};"
        : "+f"(c[0]), "+f"(c[1]), "+f"(c[2]), "+f"(c[3])
        : "r"(a0), "r"(a1), "r"(a2), "r"(a3), "r"(b0), "r"(b1));
}

// split two floats into packed bf16x2 (hi parts) + packed bf16x2 (lo parts)
__device__ __forceinline__ void split2(float v0, float v1, uint32_t& hi, uint32_t& lo) {
    __nv_bfloat16 h0 = __float2bfloat16(v0), h1 = __float2bfloat16(v1);
    __nv_bfloat16 l0 = __float2bfloat16(v0 - __bfloat162float(h0));
    __nv_bfloat16 l1 = __float2bfloat16(v1 - __bfloat162float(h1));
    hi = ((uint32_t)__bfloat16_as_ushort(h1) << 16) | __bfloat16_as_ushort(h0);
    lo = ((uint32_t)__bfloat16_as_ushort(l1) << 16) | __bfloat16_as_ushort(l0);
}

// ---------------------------------------------------------------------------
// Convert fp32 -> (bf16 hi, bf16 lo), row-major. 8 cols per thread.
// ---------------------------------------------------------------------------
__global__ __launch_bounds__(256) void convert_kernel(const float* __restrict__ src,
                                                      int sel, int rows)
{
    __nv_bfloat16 *dh, *dl;
    switch (sel) {
        case 0: dh = g_xh;  dl = g_xl;  break;
        case 1: dh = g_Wqh; dl = g_Wql; break;
        case 2: dh = g_Wkh; dl = g_Wkl; break;
        case 3: dh = g_Wvh; dl = g_Wvl; break;
        default: dh = g_Woh; dl = g_Wol; break;
    }
    int id = blockIdx.x * 256 + threadIdx.x;
    int r = id >> 7;
    if (r >= rows) return;
    int c = (id & 127) << 3;

    float4 v0 = *(const float4*)&src[(size_t)r * DIM + c];
    float4 v1 = *(const float4*)&src[(size_t)r * DIM + c + 4];
    float v[8] = {v0.x, v0.y, v0.z, v0.w, v1.x, v1.y, v1.z, v1.w};

    union { uint4 u; __nv_bfloat16 b[8]; } H, L;
#pragma unroll
    for (int i = 0; i < 8; i++) {
        __nv_bfloat16 h = __float2bfloat16(v[i]);
        H.b[i] = h;
        L.b[i] = __float2bfloat16(v[i] - __bfloat162float(h));
    }
    size_t off = (size_t)r * DIM + c;
    *(uint4*)&dh[off] = H.u;
    *(uint4*)&dl[off] = L.u;
}

// ---------------------------------------------------------------------------
// mma.sync bf16-split GEMM: C = A @ B^T, CTA 128x128, 8 warps, k-chunk 32,
// cp.async double-buffered. Epilogue modes:
//   0: fp32 + bias (final out)
//   1: split bf16 row-major * scale (Q with 0.125, K with 1.0)
//   2: split bf16 transposed [col][row] (V)
// ---------------------------------------------------------------------------
#define MM_STRIDE   40
#define MAT_BYTES   (128 * MM_STRIDE * 2)     // 10240
#define STAGE_BYTES (4 * MAT_BYTES)           // 40960
#define MM_SMEM     (2 * STAGE_BYTES)         // 81920

__device__ __forceinline__ void mm_load_chunk(uint32_t sb, int stage, int ch,
                                              const __nv_bfloat16* Ah,
                                              const __nv_bfloat16* Al,
                                              const __nv_bfloat16* Bh,
                                              const __nv_bfloat16* Bl,
                                              int mb, int nb, int tid)
{
    const uint32_t st = sb + stage * STAGE_BYTES;
#pragma unroll
    for (int it = 0; it < 2; it++) {
        int i = tid + it * 256;
        int r = i >> 2;
        int sec = i & 3;
        uint32_t d = st + r * 80 + sec * 16;
        size_t ga = (size_t)(mb * 128 + r) * DIM + ch * 32 + sec * 8;
        size_t gb = (size_t)(nb * 128 + r) * DIM + ch * 32 + sec * 8;
        CP_ASYNC16(d,                 Ah + ga);
        CP_ASYNC16(d + MAT_BYTES,     Al + ga);
        CP_ASYNC16(d + 2 * MAT_BYTES, Bh + gb);
        CP_ASYNC16(d + 3 * MAT_BYTES, Bl + gb);
    }
}

__device__ __forceinline__ void mm_tile(const __nv_bfloat16* __restrict__ Ah,
                                        const __nv_bfloat16* __restrict__ Al,
                                        const __nv_bfloat16* __restrict__ Bh,
                                        const __nv_bfloat16* __restrict__ Bl,
                                        float* __restrict__ Cf,
                                        const float* __restrict__ bias,
                                        __nv_bfloat16* __restrict__ Dh,
                                        __nv_bfloat16* __restrict__ Dl,
                                        int mode, float scale)
{
    extern __shared__ char smem[];
    const uint32_t sb = smem_u32(smem);
    const int tid  = threadIdx.x;
    const int wid  = tid >> 5;
    const int lane = tid & 31;
    const int wm   = wid & 1;
    const int wn   = wid >> 1;
    const int mb   = blockIdx.y;
    const int nb   = blockIdx.x;

    const int r4 = lane >> 2;
    const int kq = (lane & 3) * 2;

    float acc[4][4][4];
#pragma unroll
    for (int fm = 0; fm < 4; fm++)
#pragma unroll
        for (int fn = 0; fn < 4; fn++)
#pragma unroll
            for (int q = 0; q < 4; q++) acc[fm][fn][q] = 0.0f;

    mm_load_chunk(sb, 0, 0, Ah, Al, Bh, Bl, mb, nb, tid);
    CP_COMMIT();

#pragma unroll 1
    for (int ch = 0; ch < 32; ch++) {
        if (ch + 1 < 32) {
            mm_load_chunk(sb, (ch + 1) & 1, ch + 1, Ah, Al, Bh, Bl, mb, nb, tid);
            CP_COMMIT();
            CP_WAIT1();
        } else {
            CP_WAIT0();
        }
        __syncthreads();

        const uint32_t stg   = sb + (ch & 1) * STAGE_BYTES;
        const uint32_t aBase = stg + (wm * 64) * 80;
        const uint32_t bBase = stg + 2 * MAT_BYTES + (wn * 32) * 80;

#pragma unroll
        for (int ks = 0; ks < 2; ks++) {
            const uint32_t kb = (ks * 16 + kq) * 2;

            uint32_t bh[4][2], bl[4][2];
#pragma unroll
            for (int fn = 0; fn < 4; fn++) {
                uint32_t addr = bBase + (fn * 8 + r4) * 80 + kb;
                bh[fn][0] = *(const uint32_t*)(smem + (addr - sb));
                bh[fn][1] = *(const uint32_t*)(smem + (addr - sb) + 16);
                bl[fn][0] = *(const uint32_t*)(smem + (addr - sb) + MAT_BYTES);
                bl[fn][1] = *(const uint32_t*)(smem + (addr - sb) + MAT_BYTES + 16);
            }

#pragma unroll
            for (int fm = 0; fm < 4; fm++) {
                uint32_t a0a = aBase + (fm * 16 + r4) * 80 + kb;
                uint32_t ah0 = *(const uint32_t*)(smem + (a0a - sb));
                uint32_t ah1 = *(const uint32_t*)(smem + (a0a - sb) + 8 * 80);
                uint32_t ah2 = *(const uint32_t*)(smem + (a0a - sb) + 16);
                uint32_t ah3 = *(const uint32_t*)(smem + (a0a - sb) + 8 * 80 + 16);
                uint32_t al0 = *(const uint32_t*)(smem + (a0a - sb) + MAT_BYTES);
                uint32_t al1 = *(const uint32_t*)(smem + (a0a - sb) + MAT_BYTES + 8 * 80);
                uint32_t al2 = *(const uint32_t*)(smem + (a0a - sb) + MAT_BYTES + 16);
                uint32_t al3 = *(const uint32_t*)(smem + (a0a - sb) + MAT_BYTES + 8 * 80 + 16);
#pragma unroll
                for (int fn = 0; fn < 4; fn++) {
                    mma16816(acc[fm][fn], ah0, ah1, ah2, ah3, bh[fn][0], bh[fn][1]);
                    mma16816(acc[fm][fn], ah0, ah1, ah2, ah3, bl[fn][0], bl[fn][1]);
                    mma16816(acc[fm][fn], al0, al1, al2, al3, bh[fn][0], bh[fn][1]);
                }
            }
        }
        __syncthreads();
    }

    // epilogue
#pragma unroll
    for (int fm = 0; fm < 4; fm++) {
        const int row = mb * 128 + wm * 64 + fm * 16 + r4;
#pragma unroll
        for (int fn = 0; fn < 4; fn++) {
            const int col = nb * 128 + wn * 32 + fn * 8 + kq;
            float v0 = acc[fm][fn][0], v1 = acc[fm][fn][1];
            float v2 = acc[fm][fn][2], v3 = acc[fm][fn][3];
            if (mode == 0) {
                float b0 = bias ? bias[col] : 0.f, b1 = bias ? bias[col + 1] : 0.f;
                *(float2*)&Cf[(size_t)row * DIM + col] = make_float2(v0 + b0, v1 + b1);
                *(float2*)&Cf[(size_t)(row + 8) * DIM + col] = make_float2(v2 + b0, v3 + b1);
            } else if (mode == 1) {
                uint32_t hi, lo;
                split2(v0 * scale, v1 * scale, hi, lo);
                *(uint32_t*)&Dh[(size_t)row * DIM + col] = hi;
                *(uint32_t*)&Dl[(size_t)row * DIM + col] = lo;
                split2(v2 * scale, v3 * scale, hi, lo);
                *(uint32_t*)&Dh[(size_t)(row + 8) * DIM + col] = hi;
                *(uint32_t*)&Dl[(size_t)(row + 8) * DIM + col] = lo;
            } else {
                // transposed split stores: Dt[col][row]
                __nv_bfloat16 h, l;
                h = __float2bfloat16(v0); l = __float2bfloat16(v0 - __bfloat162float(h));
                Dh[(size_t)col * SEQ + row] = h;       Dl[(size_t)col * SEQ + row] = l;
                h = __float2bfloat16(v1); l = __float2bfloat16(v1 - __bfloat162float(h));
                Dh[(size_t)(col + 1) * SEQ + row] = h; Dl[(size_t)(col + 1) * SEQ + row] = l;
                h = __float2bfloat16(v2); l = __float2bfloat16(v2 - __bfloat162float(h));
                Dh[(size_t)col * SEQ + row + 8] = h;   Dl[(size_t)col * SEQ + row + 8] = l;
                h = __float2bfloat16(v3); l = __float2bfloat16(v3 - __bfloat162float(h));
                Dh[(size_t)(col + 1) * SEQ + row + 8] = h; Dl[(size_t)(col + 1) * SEQ + row + 8] = l;
            }
        }
    }
}

__global__ __launch_bounds__(256) void mm_qkv_kernel()
{
    if (blockIdx.z == 0)
        mm_tile(g_xh, g_xl, g_Wqh, g_Wql, nullptr, nullptr, g_Qh, g_Ql, 1, 0.125f);
    else if (blockIdx.z == 1)
        mm_tile(g_xh, g_xl, g_Wkh, g_Wkl, nullptr, nullptr, g_Kh, g_Kl, 1, 1.0f);
    else
        mm_tile(g_xh, g_xl, g_Wvh, g_Wvl, nullptr, nullptr, g_Vth, g_Vtl, 2, 1.0f);
}

__global__ __launch_bounds__(256) void mm_out_kernel(const float* __restrict__ bo,
                                                     float* __restrict__ out)
{
    mm_tile(g_ch, g_cl, g_Woh, g_Wol, out, bo, nullptr, nullptr, 0, 1.0f);
}

// ---------------------------------------------------------------------------
// Flash attention on mma.sync bf16-split. Br=Bc=128, 256 threads, 8 warps.
// Warp w owns q-rows [w*16, w*16+16). Q frags in registers for whole kernel.
// K tiles row-major (stride 144B), V tiles transposed (stride 272B) in smem,
// cp.async double-buffered. P stays in registers (S C-frag == PV A-frag).
// ---------------------------------------------------------------------------
#define KSTRIDE_B 144
#define VSTRIDE_B 272
#define KBYTES   (128 * KSTRIDE_B)            // 18432
#define VBYTES   (64 * VSTRIDE_B)             // 17408
#define STAGE_A  (2 * KBYTES + 2 * VBYTES)    // 71680
#define ATTN_SMEM (2 * STAGE_A)               // 143360

__global__ __launch_bounds__(256, 1) void attn_kernel()
{
    extern __shared__ char smem[];
    const uint32_t sb = smem_u32(smem);
    const int tid  = threadIdx.x;
    const int wid  = tid >> 5;
    const int lane = tid & 31;
    const int r4   = lane >> 2;
    const int kq   = (lane & 3) * 2;
    const int qb   = (gridDim.x - 1) - blockIdx.x;   // reversed: big blocks first
    const int h    = blockIdx.y;
    const int hc   = h * HD;

    const int R0 = qb * 128 + wid * 16 + r4;
    const int R1 = R0 + 8;

    // Q fragments (split), resident in registers for the whole kernel
    uint32_t qh[4][4], ql[4][4];
#pragma unroll
    for (int ks = 0; ks < 4; ks++) {
        const size_t k0 = (size_t)hc + ks * 16 + kq;
        qh[ks][0] = *(const uint32_t*)&g_Qh[(size_t)R0 * DIM + k0];
        qh[ks][1] = *(const uint32_t*)&g_Qh[(size_t)R1 * DIM + k0];
        qh[ks][2] = *(const uint32_t*)&g_Qh[(size_t)R0 * DIM + k0 + 8];
        qh[ks][3] = *(const uint32_t*)&g_Qh[(size_t)R1 * DIM + k0 + 8];
        ql[ks][0] = *(const uint32_t*)&g_Ql[(size_t)R0 * DIM + k0];
        ql[ks][1] = *(const uint32_t*)&g_Ql[(size_t)R1 * DIM + k0];
        ql[ks][2] = *(const uint32_t*)&g_Ql[(size_t)R0 * DIM + k0 + 8];
        ql[ks][3] = *(const uint32_t*)&g_Ql[(size_t)R1 * DIM + k0 + 8];
    }

    float o[8][4];
#pragma unroll
    for (int i = 0; i < 8; i++)
#pragma unroll
        for (int j = 0; j < 4; j++) o[i][j] = 0.0f;
    float m0 = -1e30f, m1 = -1e30f, l0 = 0.0f, l1 = 0.0f;

    auto load_stage = [&](int stg, int kb) {
        const uint32_t st = sb + stg * STAGE_A;
#pragma unroll
        for (int it = 0; it < 4; it++) {
            int i = tid + it * 256;              // 0..1023
            int r = i >> 3, sec = i & 7;
            uint32_t d = st + r * KSTRIDE_B + sec * 16;
            size_t g = (size_t)(kb * 128 + r) * DIM + hc + sec * 8;
            CP_ASYNC16(d, g_Kh + g);
            CP_ASYNC16(d + KBYTES, g_Kl + g);
        }
        const uint32_t vst = st + 2 * KBYTES;
#pragma unroll
        for (int it = 0; it < 4; it++) {
            int i = tid + it * 256;
            int dd = i >> 4, sec = i & 15;
            uint32_t d = vst + dd * VSTRIDE_B + sec * 16;
            size_t g = (size_t)(hc + dd) * SEQ + kb * 128 + sec * 8;
            CP_ASYNC16(d, g_Vth + g);
            CP_ASYNC16(d + VBYTES, g_Vtl + g);
        }
    };

    load_stage(0, 0);
    CP_COMMIT();

#pragma unroll 1
    for (int kb = 0; kb <= qb; kb++) {
        if (kb < qb) {
            load_stage((kb + 1) & 1, kb + 1);
            CP_COMMIT();
            CP_WAIT1();
        } else {
            CP_WAIT0();
        }
        __syncthreads();

        const char* kbase = smem + (kb & 1) * STAGE_A;
        const char* vbase = kbase + 2 * KBYTES;

        // S = Q @ K^T (3-term split)
        float s[16][4];
#pragma unroll
        for (int nf = 0; nf < 16; nf++) {
#pragma unroll
            for (int q = 0; q < 4; q++) s[nf][q] = 0.0f;
#pragma unroll
            for (int ks = 0; ks < 4; ks++) {
                const char* p = kbase + (nf * 8 + r4) * KSTRIDE_B + (ks * 16 + kq) * 2;
                uint32_t bh0 = *(const uint32_t*)p;
                uint32_t bh1 = *(const uint32_t*)(p + 16);
                uint32_t bl0 = *(const uint32_t*)(p + KBYTES);
                uint32_t bl1 = *(const uint32_t*)(p + KBYTES + 16);
                mma16816(s[nf], qh[ks][0], qh[ks][1], qh[ks][2], qh[ks][3], bh0, bh1);
                mma16816(s[nf], qh[ks][0], qh[ks][1], qh[ks][2], qh[ks][3], bl0, bl1);
                mma16816(s[nf], ql[ks][0], ql[ks][1], ql[ks][2], ql[ks][3], bh0, bh1);
            }
        }

        // causal mask (only the diagonal block needs it)
        if (kb == qb) {
#pragma unroll
            for (int nf = 0; nf < 16; nf++) {
                int C0 = kb * 128 + nf * 8 + kq;
                if (C0 > R0)     s[nf][0] = -1e30f;
                if (C0 + 1 > R0) s[nf][1] = -1e30f;
                if (C0 > R1)     s[nf][2] = -1e30f;
                if (C0 + 1 > R1) s[nf][3] = -1e30f;
            }
        }

        // online softmax, rows R0 (regs 0,1) and R1 (regs 2,3)
        {
            float mx0 = m0, mx1 = m1;
#pragma unroll
            for (int nf = 0; nf < 16; nf++) {
                mx0 = fmaxf(mx0, fmaxf(s[nf][0], s[nf][1]));
                mx1 = fmaxf(mx1, fmaxf(s[nf][2], s[nf][3]));
            }
            mx0 = fmaxf(mx0, __shfl_xor_sync(0xffffffffu, mx0, 1));
            mx0 = fmaxf(mx0, __shfl_xor_sync(0xffffffffu, mx0, 2));
            mx1 = fmaxf(mx1, __shfl_xor_sync(0xffffffffu, mx1, 1));
            mx1 = fmaxf(mx1, __shfl_xor_sync(0xffffffffu, mx1, 2));
            float fac0 = __expf(m0 - mx0);
            float fac1 = __expf(m1 - mx1);
            m0 = mx0; m1 = mx1;
            float sum0 = 0.f, sum1 = 0.f;
#pragma unroll
            for (int nf = 0; nf < 16; nf++) {
                s[nf][0] = __expf(s[nf][0] - mx0);
                s[nf][1] = __expf(s[nf][1] - mx0);
                s[nf][2] = __expf(s[nf][2] - mx1);
                s[nf][3] = __expf(s[nf][3] - mx1);
                sum0 += s[nf][0] + s[nf][1];
                sum1 += s[nf][2] + s[nf][3];
            }
            sum0 += __shfl_xor_sync(0xffffffffu, sum0, 1);
            sum0 += __shfl_xor_sync(0xffffffffu, sum0, 2);
            sum1 += __shfl_xor_sync(0xffffffffu, sum1, 1);
            sum1 += __shfl_xor_sync(0xffffffffu, sum1, 2);
            l0 = l0 * fac0 + sum0;
            l1 = l1 * fac1 + sum1;
#pragma unroll
            for (int i = 0; i < 8; i++) {
                o[i][0] *= fac0; o[i][1] *= fac0;
                o[i][2] *= fac1; o[i][3] *= fac1;
            }
        }

        // O += P @ V : P split in registers, V from transposed smem tiles
#pragma unroll
        for (int kk = 0; kk < 8; kk++) {
            uint32_t ph[4], pl[4];
            split2(s[2 * kk][0],     s[2 * kk][1],     ph[0], pl[0]);
            split2(s[2 * kk][2],     s[2 * kk][3],     ph[1], pl[1]);
            split2(s[2 * kk + 1][0], s[2 * kk + 1][1], ph[2], pl[2]);
            split2(s[2 * kk + 1][2], s[2 * kk + 1][3], ph[3], pl[3]);
#pragma unroll
            for (int onf = 0; onf < 8; onf++) {
                const char* p = vbase + (onf * 8 + r4) * VSTRIDE_B + (kk * 16 + kq) * 2;
                uint32_t bh0 = *(const uint32_t*)p;
                uint32_t bh1 = *(const uint32_t*)(p + 16);
                uint32_t bl0 = *(const uint32_t*)(p + VBYTES);
                uint32_t bl1 = *(const uint32_t*)(p + VBYTES + 16);
                mma16816(o[onf], ph[0], ph[1], ph[2], ph[3], bh0, bh1);
                mma16816(o[onf], ph[0], ph[1], ph[2], ph[3], bl0, bl1);
                mma16816(o[onf], pl[0], pl[1], pl[2], pl[3], bh0, bh1);
            }
        }
        __syncthreads();
    }

    // epilogue: normalize, split to bf16, store ctx
    const float i0 = 1.0f / l0;
    const float i1 = 1.0f / l1;
#pragma unroll
    for (int onf = 0; onf < 8; onf++) {
        uint32_t hi, lo;
        const size_t c0 = (size_t)hc + onf * 8 + kq;
        split2(o[onf][0] * i0, o[onf][1] * i0, hi, lo);
        *(uint32_t*)&g_ch[(size_t)R0 * DIM + c0] = hi;
        *(uint32_t*)&g_cl[(size_t)R0 * DIM + c0] = lo;
        split2(o[onf][2] * i1, o[onf][3] * i1, hi, lo);
        *(uint32_t*)&g_ch[(size_t)R1 * DIM + c0] = hi;
        *(uint32_t*)&g_cl[(size_t)R1 * DIM + c0] = lo;
    }
}

extern "C" void kernel_launch(void* const* d_in, const int* in_sizes, int n_in,
                              void* d_out, int out_size)
{
    (void)in_sizes; (void)n_in; (void)out_size;
    const float* x  = (const float*)d_in[0];
    const float* Wq = (const float*)d_in[1];
    const float* Wk = (const float*)d_in[2];
    const float* Wv = (const float*)d_in[3];
    const float* Wo = (const float*)d_in[4];
    const float* bo = (const float*)d_in[5];
    float* out = (float*)d_out;

    static bool attr_set = false;
    if (!attr_set) {
        cudaFuncSetAttribute(attn_kernel,
                             cudaFuncAttributeMaxDynamicSharedMemorySize, ATTN_SMEM);
        cudaFuncSetAttribute(mm_qkv_kernel,
                             cudaFuncAttributeMaxDynamicSharedMemorySize, MM_SMEM);
        cudaFuncSetAttribute(mm_out_kernel,
                             cudaFuncAttributeMaxDynamicSharedMemorySize, MM_SMEM);
        attr_set = true;
    }

    // 1) bf16-split conversions (x + 4 weights)
    convert_kernel<<<SEQ * 128 / 256, 256>>>(x,  0, SEQ);
    convert_kernel<<<DIM * 128 / 256, 256>>>(Wq, 1, DIM);
    convert_kernel<<<DIM * 128 / 256, 256>>>(Wk, 2, DIM);
    convert_kernel<<<DIM * 128 / 256, 256>>>(Wv, 3, DIM);
    convert_kernel<<<DIM * 128 / 256, 256>>>(Wo, 4, DIM);

    // 2) Q/K/V projections; epilogues emit split-bf16 (Q scaled, V transposed)
    {
        dim3 grid(DIM / 128, SEQ / 128, 3);
        mm_qkv_kernel<<<grid, 256, MM_SMEM>>>();
    }
    // 3) causal flash attention on tensor cores
    {
        dim3 grid(SEQ / 128, NH);
        attn_kernel<<<grid, 256, ATTN_SMEM>>>();
    }
    // 4) output projection + bias
    {
        dim3 grid(DIM / 128, SEQ / 128, 1);
        mm_out_kernel<<<grid, 256, MM_SMEM>>>(bo, out);
    }
}